// round 17
// baseline (speedup 1.0000x reference)
#include <cuda_runtime.h>
#include <cstdint>

// Problem constants (fixed by setup_inputs)
#define BT 4
#define NV 20000
#define NF 40000
#define HH 256
#define WW 256
#define SS 2048
#define NBIN 256
#define RBINSCALE 64.0f        // bin = r * 64, range [0,4), clamp 255
#define VSLOT 20480            // per-batch vert slots (NV + pad, even)
#define NPAIRB (VSLOT / 2)     // 10240 pairs per batch
#define SPB 32                 // samples per block
#define GRID (BT * (SS / SPB)) // 256 main blocks
#define MASK_PENALTY 1000.0f
#define BIGW 3.0e37f

typedef unsigned long long u64;

// Scratch (no dynamic allocation allowed).
// g_visible: zeroed by k_vis, marked by k_f2v, read by k_scatter.
// g_faceVis: all-zero invariant (k_f2v restores). Hists zeroed by k_vis.
// g_vcur/g_scur rewritten by k_scan each launch. g_hasInv set by k_scatter,
// reset by k_main's final block. g_done self-resets. Deterministic values.
__device__ unsigned char g_visible[BT * NV];
__device__ unsigned char g_faceVis[BT * NF];
__device__ int   g_vhist[BT * NBIN];
__device__ int   g_shist[BT * NBIN];
__device__ int   g_vstart[BT * (NBIN + 1)];
__device__ int   g_sstart[BT * (NBIN + 1)];
__device__ int   g_vcur[BT * NBIN];
__device__ int   g_scur[BT * NBIN];
// radius-sorted verts, pair-packed: per pair {x0,x1}{y0,y1}{z0,z1}{w0,w1}
__device__ float g_vp[(size_t)BT * NPAIRB * 8];
__device__ int   g_sIdx[BT * SS];      // radius-sorted sample -> original idx
__device__ float g_minf[BT * SS];      // per-sample min score (w - s.v)
__device__ int   g_hasInv[BT];
__device__ int   g_done = 0;

// ---- packed f32x2 helpers (sm_103a) ----
__device__ __forceinline__ u64 pack2(float lo, float hi) {
    u64 r; asm("mov.b64 %0, {%1, %2};" : "=l"(r) : "f"(lo), "f"(hi)); return r;
}
__device__ __forceinline__ u64 fma2(u64 a, u64 b, u64 c) {
    u64 d; asm("fma.rn.f32x2 %0, %1, %2, %3;" : "=l"(d) : "l"(a), "l"(b), "l"(c)); return d;
}
__device__ __forceinline__ int rbin(float r) {
    int b = (int)(r * RBINSCALE);
    return b > 255 ? 255 : b;
}

// ---------------------------------------------------------------------------
// K1: zero hists + g_visible; pixel -> face visibility.
// ---------------------------------------------------------------------------
__global__ void k_vis(const int* __restrict__ p2f) {
    int p = blockIdx.x * blockDim.x + threadIdx.x;   // < 262144
    if (p < BT * NBIN)            g_vhist[p] = 0;
    else if (p < 2 * BT * NBIN)   g_shist[p - BT * NBIN] = 0;
    if (p < (BT * NV) / 16)
        ((uint4*)g_visible)[p] = make_uint4(0, 0, 0, 0);
    int fi = __ldg(p2f + p);
    if ((unsigned)fi < (unsigned)(BT * NF))          // rejects -1
        g_faceVis[fi] = 1;
}

// ---------------------------------------------------------------------------
// K2: face -> vert visibility (restore faceVis) + radius histograms
// for verts (80000) and samples (8192).
// ---------------------------------------------------------------------------
__global__ void k_f2v(const int* __restrict__ faces,
                      const float* __restrict__ verts,
                      const float* __restrict__ bds) {
    int fi = blockIdx.x * blockDim.x + threadIdx.x;  // < 160000

    // vert radius histogram
    if (fi < BT * NV) {
        int b = fi / NV;
        const float* vp = verts + fi * 3;
        float x = __ldg(vp), y = __ldg(vp + 1), z = __ldg(vp + 2);
        float r = sqrtf(x * x + y * y + z * z);
        atomicAdd(&g_vhist[b * NBIN + rbin(r)], 1);
    }
    // sample radius histogram
    if (fi < BT * SS) {
        int b = fi >> 11;
        float4 s = ((const float4*)bds)[fi];
        float r = sqrtf(s.x * s.x + s.y * s.y + s.z * s.z);
        atomicAdd(&g_shist[b * NBIN + rbin(r)], 1);
    }

    bool vis = (g_faceVis[fi] != 0);
    g_faceVis[fi] = 0;                               // restore invariant
    if (!vis) return;
    int b = fi / NF;
    const int* fr = faces + fi * 3;
    int v0 = __ldg(fr), v1 = __ldg(fr + 1), v2 = __ldg(fr + 2);
    int base = b * NV;
    if ((unsigned)v0 < (unsigned)NV) g_visible[base + v0] = 1;
    if ((unsigned)v1 < (unsigned)NV) g_visible[base + v1] = 1;
    if ((unsigned)v2 < (unsigned)NV) g_visible[base + v2] = 1;
}

// ---------------------------------------------------------------------------
// K3: prefix scans of the 8 histograms -> bin starts + cursors.
// ---------------------------------------------------------------------------
__global__ void k_scan() {
    __shared__ int sc[256];
    int t = threadIdx.x;
    for (int h = 0; h < 2 * BT; h++) {
        int* hist  = (h < BT) ? &g_vhist[h * NBIN]        : &g_shist[(h - BT) * NBIN];
        int* start = (h < BT) ? &g_vstart[h * (NBIN + 1)] : &g_sstart[(h - BT) * (NBIN + 1)];
        int* cur   = (h < BT) ? &g_vcur[h * NBIN]         : &g_scur[(h - BT) * NBIN];
        int v = hist[t];
        sc[t] = v;
        __syncthreads();
        for (int off = 1; off < 256; off <<= 1) {
            int x = (t >= off) ? sc[t - off] : 0;
            __syncthreads();
            sc[t] += x;
            __syncthreads();
        }
        start[t] = sc[t] - v;
        cur[t]   = sc[t] - v;
        if (t == 255) start[256] = sc[255];
        __syncthreads();
    }
}

// ---------------------------------------------------------------------------
// K4: scatter verts into radius-sorted pair-packed layout (+pads) and
// samples into radius-sorted index array. Sets g_hasInv.
// ---------------------------------------------------------------------------
__global__ void k_scatter(const float* __restrict__ verts,
                          const float* __restrict__ bds) {
    int tid = blockIdx.x * blockDim.x + threadIdx.x;
    if (tid < BT * VSLOT) {
        int b = tid / VSLOT;
        int u = tid - b * VSLOT;
        if (u < NV) {
            const float* vp = verts + (b * NV + u) * 3;
            float x = __ldg(vp), y = __ldg(vp + 1), z = __ldg(vp + 2);
            float r = sqrtf(x * x + y * y + z * z);
            int bin = rbin(r);
            int pos = atomicAdd(&g_vcur[b * NBIN + bin], 1);  // [0, NV)
            bool vis = (g_visible[b * NV + u] != 0);
            float w = vis ? 0.5f * (x * x + y * y + z * z) : BIGW;
            if (!vis) g_hasInv[b] = 1;
            float* o = g_vp + ((size_t)b * NPAIRB + (pos >> 1)) * 8;
            int hh = pos & 1;
            o[hh] = x; o[2 + hh] = y; o[4 + hh] = z; o[6 + hh] = w;
        } else {                                              // pad slots
            float* o = g_vp + ((size_t)b * NPAIRB + (u >> 1)) * 8;
            int hh = u & 1;
            o[hh] = 0.f; o[2 + hh] = 0.f; o[4 + hh] = 0.f; o[6 + hh] = BIGW;
        }
    } else {
        int i = tid - BT * VSLOT;                             // sample slice
        if (i < BT * SS) {
            int b = i >> 11;
            float4 s = ((const float4*)bds)[i];
            float r = sqrtf(s.x * s.x + s.y * s.y + s.z * s.z);
            int bin = rbin(r);
            int pos = atomicAdd(&g_scur[b * NBIN + bin], 1);  // [0, SS)
            g_sIdx[b * SS + pos] = i & 2047;                  // original idx
        }
    }
}

// ---------------------------------------------------------------------------
// K5: main pruned min-score kernel + fused final reduce.
// Grid: 256 blocks = BT x 64 groups of 32 radius-adjacent samples.
// Phase 1: scan bins [B0-4, B1+4] -> per-lane bound u.
// Phase 2: scan remaining bins in [rs_min-delta, rs_max+delta] (exact).
// ---------------------------------------------------------------------------
__global__ void __launch_bounds__(256)
k_main(const float* __restrict__ bds, float* __restrict__ out) {
    __shared__ float sred[8][32];
    __shared__ float rbuf[256];
    __shared__ float s_flag;

    const int bx   = blockIdx.x;          // 0..255
    const int b    = bx >> 6;
    const int g    = bx & 63;
    const int t    = threadIdx.x;
    const int wid  = t >> 5;
    const int lane = t & 31;

    const int  sidx = g_sIdx[b * SS + g * SPB + lane];        // original idx
    const float4 s  = ((const float4*)bds)[b * SS + sidx];
    const float d   = s.x * s.x + s.y * s.y + s.z * s.z;      // |s|^2
    const float rs  = sqrtf(d);
    const u64 nx = pack2(-s.x, -s.x);
    const u64 ny = pack2(-s.y, -s.y);
    const u64 nz = pack2(-s.z, -s.z);
    float mE = BIGW, mO = BIGW;

    // block sample-bin range (identical in all warps)
    int B0 = rbin(rs), B1 = B0;
    float rsmin = rs, rsmax = rs;
    #pragma unroll
    for (int o = 16; o; o >>= 1) {
        B0    = min(B0,    __shfl_xor_sync(0xffffffffu, B0, o));
        B1    = max(B1,    __shfl_xor_sync(0xffffffffu, B1, o));
        rsmin = fminf(rsmin, __shfl_xor_sync(0xffffffffu, rsmin, o));
        rsmax = fmaxf(rsmax, __shfl_xor_sync(0xffffffffu, rsmax, o));
    }

    const int* vstart = g_vstart + b * (NBIN + 1);
    const float* vbase = g_vp + (size_t)b * NPAIRB * 8;

    const int lo1 = max(B0 - 4, 0);
    const int hi1 = min(B1 + 4, 255);

    // ---- phase 1: scan [lo1, hi1] ----
    {
        int pl = vstart[lo1] >> 1;
        int ph = (vstart[hi1 + 1] + 1) >> 1;
        #pragma unroll 4
        for (int i = pl + wid; i < ph; i += 8) {
            const ulonglong2* vp = (const ulonglong2*)(vbase + (size_t)i * 8);
            ulonglong2 a = __ldg(vp);
            ulonglong2 c = __ldg(vp + 1);
            u64 acc = fma2(a.x, nx, fma2(a.y, ny, fma2(c.x, nz, c.y)));
            mE = fminf(mE, __uint_as_float((unsigned)acc));
            mO = fminf(mO, __uint_as_float((unsigned)(acc >> 32)));
        }
    }
    sred[wid][lane] = fminf(mE, mO);
    __syncthreads();

    // per-lane bound u (min over warps), block-max distance bound
    float u = sred[0][lane];
    #pragma unroll
    for (int w = 1; w < 8; w++) u = fminf(u, sred[w][lane]);
    float ud = fmaxf(2.0f * u + d, 0.0f);                    // distance^2 bound
    #pragma unroll
    for (int o = 16; o; o >>= 1)
        ud = fmaxf(ud, __shfl_xor_sync(0xffffffffu, ud, o));
    float delta = sqrtf(ud * 1.0002f) + 1e-5f;               // safety margin

    const int lo2 = rbin(fmaxf(rsmin - delta, 0.0f));
    const int hi2 = rbin(rsmax + delta);

    // ---- phase 2: scan [lo2, lo1) and (hi1, hi2] ----
    if (lo2 < lo1) {
        int pl = vstart[lo2] >> 1;
        int ph = (vstart[lo1] + 1) >> 1;
        #pragma unroll 4
        for (int i = pl + wid; i < ph; i += 8) {
            const ulonglong2* vp = (const ulonglong2*)(vbase + (size_t)i * 8);
            ulonglong2 a = __ldg(vp);
            ulonglong2 c = __ldg(vp + 1);
            u64 acc = fma2(a.x, nx, fma2(a.y, ny, fma2(c.x, nz, c.y)));
            mE = fminf(mE, __uint_as_float((unsigned)acc));
            mO = fminf(mO, __uint_as_float((unsigned)(acc >> 32)));
        }
    }
    if (hi2 > hi1) {
        int pl = vstart[hi1 + 1] >> 1;
        int ph = (vstart[hi2 + 1] + 1) >> 1;
        #pragma unroll 4
        for (int i = pl + wid; i < ph; i += 8) {
            const ulonglong2* vp = (const ulonglong2*)(vbase + (size_t)i * 8);
            ulonglong2 a = __ldg(vp);
            ulonglong2 c = __ldg(vp + 1);
            u64 acc = fma2(a.x, nx, fma2(a.y, ny, fma2(c.x, nz, c.y)));
            mE = fminf(mE, __uint_as_float((unsigned)acc));
            mO = fminf(mO, __uint_as_float((unsigned)(acc >> 32)));
        }
    }
    __syncthreads();
    sred[wid][lane] = fminf(mE, mO);
    __syncthreads();

    if (wid == 0) {
        float mm = sred[0][lane];
        #pragma unroll
        for (int w = 1; w < 8; w++) mm = fminf(mm, sred[w][lane]);
        g_minf[b * SS + sidx] = mm;          // unique writer per sample
    }

    // ---- last-block final reduction ----
    __threadfence();
    __syncthreads();
    if (t == 0)
        s_flag = (atomicAdd(&g_done, 1) == GRID - 1) ? 1.0f : 0.0f;
    __syncthreads();
    if (s_flag == 0.0f) return;

    if (t == 0) g_done = 0;                  // reset for next graph replay

    float acc = 0.0f;
    const float4* bq = (const float4*)bds;
    #pragma unroll
    for (int k = 0; k < (BT * SS) / 256; k++) {
        int i = t + k * 256;
        int bb = i >> 11;                    // SS = 2048
        float m = g_minf[i];
        float4 sm = bq[i];
        float ss2 = sm.x * sm.x + sm.y * sm.y + sm.z * sm.z;
        float dist = 2.0f * m + ss2;
        if (g_hasInv[bb]) dist = fminf(dist, MASK_PENALTY);
        acc += dist * sm.w;                  // sample mask (0/1)
    }
    rbuf[t] = acc;
    __syncthreads();                         // also orders g_hasInv reads
    if (t < BT) g_hasInv[t] = 0;             // reset for next replay
    #pragma unroll
    for (int sft = 128; sft > 0; sft >>= 1) {
        if (t < sft) rbuf[t] += rbuf[t + sft];
        __syncthreads();
    }
    if (t == 0) out[0] = rbuf[0] * (1.0f / BT);
}

// ---------------------------------------------------------------------------
// Launch — 5 kernels.
// Inputs (metadata order): verts f32, bds f32, faces int32, pix_to_face int32,
// n_samples (ignored; fixed = 2048). Output: scalar f32.
// ---------------------------------------------------------------------------
extern "C" void kernel_launch(void* const* d_in, const int* in_sizes, int n_in,
                              void* d_out, int out_size) {
    const float* verts = (const float*)d_in[0];
    const float* bds   = (const float*)d_in[1];
    const int*   faces = (const int*)d_in[2];
    const int*   p2f   = (const int*)d_in[3];
    float* out = (float*)d_out;

    k_vis<<<(BT * HH * WW) / 256, 256>>>(p2f);
    k_f2v<<<(BT * NF) / 256, 256>>>(faces, verts, bds);
    k_scan<<<1, 256>>>();
    k_scatter<<<(BT * VSLOT + BT * SS + 255) / 256, 256>>>(verts, bds);
    k_main<<<GRID, 256>>>(bds, out);
}